// round 1
// baseline (speedup 1.0000x reference)
#include <cuda_runtime.h>

// ---------------------------------------------------------------------------
// HebbianConv2d: valid 3x3 conv (16,256,56,56)->(16,384,54,54), per-pixel
// channel winner-take-all, Gaussian lateral feedback gating.
//
// Kernel 1: fp32 implicit-GEMM conv using packed fma.rn.f32x2 (2 FMA/instr),
//           writes y in pixel-major layout to a __device__ scratch buffer.
// Kernel 2: per-pixel argmax + Gaussian LFB gating, writes NCHW output.
// ---------------------------------------------------------------------------

#define B_SZ   16
#define CIN_   256
#define COUT_  384
#define HIN_   56
#define HO_    54
#define NPIX   46656           // 16*54*54
#define NTILE  365             // ceil(46656/128)
#define NPIX_P 46720           // 365*128
#define KDIM   2304            // 256*9

typedef unsigned long long ull;

// 71.76 MB scratch: y in pixel-major layout [pixel][cout]
__device__ float g_y[(size_t)NPIX_P * COUT_];

__device__ __forceinline__ void ffma2(ull &c, ull a, ull b) {
    asm("fma.rn.f32x2 %0, %1, %2, %0;" : "+l"(c) : "l"(a), "l"(b));
}

// ---------------------------------------------------------------------------
// Kernel 1: implicit GEMM  y[m,n] = sum_k W[m,k] * X[pix(n) + off(k)]
//   m = cout (384), n = flattened pixel (b,h,w), k = ci*9 + kh*3 + kw
// Block tile: 128(m) x 128(n) x 8(k). 256 threads, 8x8 microtile per thread
// held as 8 x 4 f32x2 accumulators (n-pairs).
// ---------------------------------------------------------------------------
__global__ __launch_bounds__(256, 2)
void conv_gemm_kernel(const float* __restrict__ X, const float* __restrict__ Wg)
{
    __shared__ float2 As[8][128];   // A duplicated: {a,a} per element (8 KB)
    __shared__ float  Bs[8][128];   // 4 KB
    __shared__ int    pixBase[128];

    const int tid = threadIdx.x;
    const int m0  = blockIdx.y * 128;
    const int n0  = blockIdx.x * 128;
    const int tx  = tid & 15;       // n group
    const int ty  = tid >> 4;       // m group

    // per-block pixel base offsets: x[b,0,h,w]
    if (tid < 128) {
        int n = n0 + tid;
        if (n > NPIX - 1) n = NPIX - 1;       // clamp padded tail
        int b = n / (HO_ * HO_);
        int r = n - b * (HO_ * HO_);
        int h = r / HO_;
        int w = r - h * HO_;
        pixBase[tid] = b * (CIN_ * HIN_ * HIN_) + h * HIN_ + w;
    }
    __syncthreads();

    // load roles
    const int arow = tid >> 1;            // 0..127 (m within tile)
    const int akq  = (tid & 1) * 4;       // k offset 0 or 4
    const int bk   = tid >> 5;            // 0..7  (k within step)
    const int bn   = (tid & 31) * 4;      // 0..124 (n within tile)

    const float* Arow = Wg + (size_t)(m0 + arow) * KDIM + akq;

    ull acc[8][4];
#pragma unroll
    for (int i = 0; i < 8; i++)
#pragma unroll
        for (int j = 0; j < 4; j++) acc[i][j] = 0ull;

    const int pb0 = pixBase[bn + 0];
    const int pb1 = pixBase[bn + 1];
    const int pb2 = pixBase[bn + 2];
    const int pb3 = pixBase[bn + 3];

    for (int k0 = 0; k0 < KDIM; k0 += 8) {
        // ---- issue global loads (overlap with previous compute phase) ----
        float4 av = *(const float4*)(Arow + k0);

        int k  = k0 + bk;
        int ci = k / 9;
        int r9 = k - ci * 9;
        int kh = r9 / 3;
        int kw = r9 - kh * 3;
        int off = ci * (HIN_ * HIN_) + kh * HIN_ + kw;
        float bv0 = X[pb0 + off];
        float bv1 = X[pb1 + off];
        float bv2 = X[pb2 + off];
        float bv3 = X[pb3 + off];

        __syncthreads();   // previous compute done; smem free to overwrite

        As[akq + 0][arow] = make_float2(av.x, av.x);
        As[akq + 1][arow] = make_float2(av.y, av.y);
        As[akq + 2][arow] = make_float2(av.z, av.z);
        As[akq + 3][arow] = make_float2(av.w, av.w);
        Bs[bk][bn + 0] = bv0;
        Bs[bk][bn + 1] = bv1;
        Bs[bk][bn + 2] = bv2;
        Bs[bk][bn + 3] = bv3;

        __syncthreads();

        // ---- compute 8 k-slices ----
#pragma unroll
        for (int kk = 0; kk < 8; kk++) {
            const ulonglong2* ap = (const ulonglong2*)&As[kk][ty * 8];
            ulonglong2 a01 = ap[0], a23 = ap[1], a45 = ap[2], a67 = ap[3];
            ull a[8] = { a01.x, a01.y, a23.x, a23.y, a45.x, a45.y, a67.x, a67.y };

            const ulonglong2* bp = (const ulonglong2*)&Bs[kk][tx * 8];
            ulonglong2 b01 = bp[0], b23 = bp[1];
            ull bb[4] = { b01.x, b01.y, b23.x, b23.y };

#pragma unroll
            for (int mi = 0; mi < 8; mi++)
#pragma unroll
                for (int nj = 0; nj < 4; nj++)
                    ffma2(acc[mi][nj], a[mi], bb[nj]);
        }
    }

    // ---- store: pixel-major scratch g_y[n][m] ----
    union { ull u; float f[2]; } cv;
#pragma unroll
    for (int nj = 0; nj < 4; nj++) {
#pragma unroll
        for (int half = 0; half < 2; half++) {
            int n = n0 + tx * 8 + nj * 2 + half;
            float v[8];
#pragma unroll
            for (int mi = 0; mi < 8; mi++) { cv.u = acc[mi][nj]; v[mi] = cv.f[half]; }
            float* dst = g_y + (size_t)n * COUT_ + m0 + ty * 8;
            *(float4*)(dst + 0) = make_float4(v[0], v[1], v[2], v[3]);
            *(float4*)(dst + 4) = make_float4(v[4], v[5], v[6], v[7]);
        }
    }
}

// ---------------------------------------------------------------------------
// Kernel 2: WTA + Gaussian lateral feedback gating.
// Block = 27 pixels (half a w-row) x 384 channels. grid (2, 54, 16).
//   lfb[c] = clip( sum_{winners w'} [ -191 <= w'-c <= 192 ] *
//                  exp(-(w'-c)^2 / (2*191^2)), <=1 )
//   out[b,c,h,w] = lfb[c] * y[b,c,h,w]
// ---------------------------------------------------------------------------
#define SYP 388   // padded channel stride in smem (bank spread, 16B aligned)

__global__ __launch_bounds__(256)
void wta_lfb_kernel(float* __restrict__ out)
{
    __shared__ float sy[27 * SYP];
    __shared__ int   wcnt[27];
    __shared__ int   wlist[27][4];

    const int tid = threadIdx.x;
    const int b   = blockIdx.z;
    const int h   = blockIdx.y;
    const int w0  = blockIdx.x * 27;

    const size_t base = ((size_t)(b * HO_ + h) * HO_ + w0) * COUT_;

    // load 27 pixels x 384 channels (contiguous in g_y), pad to stride 388
    for (int i4 = tid; i4 < 27 * 96; i4 += 256) {
        float4 v = *(const float4*)(g_y + base + (size_t)i4 * 4);
        int j  = i4 / 96;
        int c4 = i4 - j * 96;
        *(float4*)&sy[j * SYP + c4 * 4] = v;
    }
    if (tid < 27) wcnt[tid] = 0;
    __syncthreads();

    // per-pixel argmax (tie-safe: collect all channels equal to max)
    const int wid  = tid >> 5;
    const int lane = tid & 31;
    for (int j = wid; j < 27; j += 8) {
        const float* p = &sy[j * SYP];
        float mx = -3.4e38f;
#pragma unroll
        for (int q = 0; q < 12; q++) mx = fmaxf(mx, p[lane + q * 32]);
#pragma unroll
        for (int o = 16; o; o >>= 1) mx = fmaxf(mx, __shfl_xor_sync(0xffffffffu, mx, o));
#pragma unroll
        for (int q = 0; q < 12; q++) {
            int c = lane + q * 32;
            if (p[c] == mx) {
                int pos = atomicAdd(&wcnt[j], 1);
                if (pos < 4) wlist[j][pos] = c;
            }
        }
    }
    __syncthreads();

    const float inv2s2 = 1.0f / (2.0f * 191.0f * 191.0f);
    for (int i = tid; i < COUT_ * 27; i += 256) {
        int c = i / 27;
        int j = i - c * 27;
        float yv = sy[j * SYP + c];
        int nw = wcnt[j]; if (nw > 4) nw = 4;
        float lfb = 0.0f;
        for (int t = 0; t < nw; t++) {
            int d = wlist[j][t] - c;           // w' - c
            if (d >= -191 && d <= 192)
                lfb += __expf(-(float)(d * d) * inv2s2);
        }
        lfb = fminf(lfb, 1.0f);
        out[(((size_t)b * COUT_ + c) * HO_ + h) * HO_ + w0 + j] = lfb * yv;
    }
}

// ---------------------------------------------------------------------------
extern "C" void kernel_launch(void* const* d_in, const int* in_sizes, int n_in,
                              void* d_out, int out_size)
{
    const float* x = (const float*)d_in[0];   // (16,256,56,56)
    const float* w = (const float*)d_in[1];   // (384,256,3,3)
    float* out = (float*)d_out;               // (16,384,54,54)

    dim3 g1(NTILE, 3);
    conv_gemm_kernel<<<g1, 256>>>(x, w);

    dim3 g2(2, HO_, B_SZ);
    wta_lfb_kernel<<<g2, 256>>>(out);
}

// round 3
// speedup vs baseline: 1.3525x; 1.3525x over previous
#include <cuda_runtime.h>
#include <cstdint>

// ---------------------------------------------------------------------------
// HebbianConv2d (sm_103 baseline ISA — no tcgen05 available in this target):
//   valid 3x3 conv (16,256,56,56)->(16,384,54,54) as implicit GEMM on the
//   FFMA f32x2 pipe, with padded-row contiguity so B-operand loads are
//   vectorized float4 streams (fixes the LDG-issue bottleneck of R1),
//   then per-pixel WTA + Gaussian lateral-feedback gating.
// ---------------------------------------------------------------------------

#define B_SZ   16
#define CIN_   256
#define COUT_  384
#define HIN_   56
#define HO_    54
#define KDIM   2304                 // 256*9
#define IMG_N  3072                 // padded local-n per image (54*56=3024 -> 3072)
#define NPAD   (B_SZ * IMG_N)       // 49152
#define IMG_SZ (CIN_ * HIN_ * HIN_) // 802816 floats per image
#define XELEMS ((size_t)B_SZ * IMG_SZ)

typedef unsigned long long ull;

__device__ float g_x[XELEMS + 4160];            // padded copy of x (slack for window reads)
__device__ float g_y[(size_t)NPAD * COUT_];     // pixel-major [padded n][cout]  (75.5 MB)
__device__ float g_pad;                         // dummy for profiler-alignment kernel

__device__ __forceinline__ void ffma2(ull &c, ull a, ull b) {
    asm("fma.rn.f32x2 %0, %1, %2, %0;" : "+l"(c) : "l"(a), "l"(b));
}
__device__ __forceinline__ ull dup2(float a) {
    ull r;
    asm("mov.b64 %0, {%1, %1};" : "=l"(r) : "f"(a));
    return r;
}

// ---------------------------------------------------------------------------
// copy x into padded __device__ buffer (also gives deterministic slack reads)
// ---------------------------------------------------------------------------
__global__ void copy_x_kernel(const float* __restrict__ x) {
    size_t i = (size_t)blockIdx.x * 256 + threadIdx.x;
    if (i < XELEMS / 4) ((float4*)g_x)[i] = ((const float4*)x)[i];
}

__global__ void pad_kernel() { if (threadIdx.x == 0) g_pad = 1.0f; }

// ---------------------------------------------------------------------------
// Conv GEMM: y[m][n] = sum_k W[m][k] * X[img(n) + off(k) + nl(n)]
//   CTA tile: M=128 x N=256, k-stage 16, double-buffered, 512 threads.
//   B rows (fixed k) are n-contiguous thanks to 56-wide padded rows; the
//   kw misalignment (4B/8B) is resolved with a shuffle funnel.
// ---------------------------------------------------------------------------
__global__ __launch_bounds__(512, 1)
void conv_gemm_kernel(const float* __restrict__ Wg)
{
    __shared__ float As[2][16][128];   // [buf][k][m]
    __shared__ float Bs[2][16][256];   // [buf][k][n]

    const int tid  = threadIdx.x;
    const int lane = tid & 31;
    const int wid  = tid >> 5;          // 0..15
    const int ty8  = wid * 8;           // m sub-offset
    const int tx   = lane;              // n group
    const int m0   = blockIdx.y * 128;

    const int bimg = blockIdx.x / 12;            // image
    const int nl0  = (blockIdx.x - bimg * 12) * 256;  // local padded n base
    const int imgb = bimg * IMG_SZ;

    // A-load role: 1 float4 per thread per stage
    const int arow = tid >> 2;          // 0..127
    const int akq  = (tid & 3) * 4;     // k offset 0,4,8,12
    const float* Abase = Wg + (size_t)(m0 + arow) * KDIM + akq;

    // B-load role: warp 'wid' owns k-row (k0 + wid)
    // decomposition of k is per-stage

    ull acc[8][4];
#pragma unroll
    for (int i = 0; i < 8; i++)
#pragma unroll
        for (int j = 0; j < 4; j++) acc[i][j] = 0ull;

    float4 av;                 // staged A
    float4 v0, v1; float2 e;   // staged B window
    int kwv = 0;

    // ---- stage loader (LDG only) ----
    auto load_stage = [&](int s) {
        int k0 = s * 16;
        av = *(const float4*)(Abase + k0);
        int k  = k0 + wid;
        int ci = k / 9;
        int r  = k - ci * 9;
        int kh = r / 3;
        kwv    = r - kh * 3;
        const float4* G4 = (const float4*)(g_x + imgb + ci * (HIN_ * HIN_)
                                           + kh * HIN_ + nl0);
        v0 = G4[lane];
        v1 = G4[lane + 32];
        e  = make_float2(0.f, 0.f);
        if (lane == 31) e = *(const float2*)(G4 + 64);
    };

    // ---- stage store (shuffle funnel + STS) ----
    auto store_stage = [&](int buf) {
        // A: scatter 4 scalars into [k][m]
        As[buf][akq + 0][arow] = av.x;
        As[buf][akq + 1][arow] = av.y;
        As[buf][akq + 2][arow] = av.z;
        As[buf][akq + 3][arow] = av.w;

        const unsigned FULL = 0xffffffffu;
        // neighbors for chunk0 (out f = lane): next float4 = v0(lane+1) | v1(lane0)
        float shx0 = __shfl_down_sync(FULL, v0.x, 1);
        float shy0 = __shfl_down_sync(FULL, v0.y, 1);
        float w32x = __shfl_sync(FULL, v1.x, 0);
        float w32y = __shfl_sync(FULL, v1.y, 0);
        float nx0 = (lane == 31) ? w32x : shx0;
        float ny0 = (lane == 31) ? w32y : shy0;
        // neighbors for chunk1 (out f = 32+lane): v1(lane+1) | e(lane31)
        float shx1 = __shfl_down_sync(FULL, v1.x, 1);
        float shy1 = __shfl_down_sync(FULL, v1.y, 1);
        float ex = __shfl_sync(FULL, e.x, 31);
        float ey = __shfl_sync(FULL, e.y, 31);
        float nx1 = (lane == 31) ? ex : shx1;
        float ny1 = (lane == 31) ? ey : shy1;

        float4 o0, o1;
        if (kwv == 0) {
            o0 = v0; o1 = v1;
        } else if (kwv == 1) {
            o0 = make_float4(v0.y, v0.z, v0.w, nx0);
            o1 = make_float4(v1.y, v1.z, v1.w, nx1);
        } else {
            o0 = make_float4(v0.z, v0.w, nx0, ny0);
            o1 = make_float4(v1.z, v1.w, nx1, ny1);
        }
        *(float4*)&Bs[buf][wid][lane * 4]       = o0;
        *(float4*)&Bs[buf][wid][128 + lane * 4] = o1;
    };

    // ---- compute one stage (16 k-slices) ----
    auto compute_stage = [&](int buf) {
#pragma unroll
        for (int kk = 0; kk < 16; kk++) {
            float4 fa0 = *(const float4*)&As[buf][kk][ty8];
            float4 fa1 = *(const float4*)&As[buf][kk][ty8 + 4];
            float a[8] = { fa0.x, fa0.y, fa0.z, fa0.w, fa1.x, fa1.y, fa1.z, fa1.w };

            ulonglong2 b01 = *(const ulonglong2*)&Bs[buf][kk][tx * 8];
            ulonglong2 b23 = *(const ulonglong2*)&Bs[buf][kk][tx * 8 + 4];
            ull bb[4] = { b01.x, b01.y, b23.x, b23.y };

#pragma unroll
            for (int mi = 0; mi < 8; mi++) {
                ull am = dup2(a[mi]);
#pragma unroll
                for (int nj = 0; nj < 4; nj++) ffma2(acc[mi][nj], am, bb[nj]);
            }
        }
    };

    // ---- pipeline: 144 stages, double buffered, one sync per stage ----
    load_stage(0);
    store_stage(0);
    __syncthreads();
    for (int s = 0; s < 143; s++) {
        load_stage(s + 1);          // LDG latency hidden under compute
        compute_stage(s & 1);
        store_stage((s + 1) & 1);   // writes the other buffer
        __syncthreads();
    }
    compute_stage(1);               // stage 143 -> buf 1

    // ---- store: g_y[padded n][m], m-contiguous per pixel ----
    const int n0g = bimg * IMG_N + nl0;
    union { ull u; float f[2]; } cv;
#pragma unroll
    for (int nj = 0; nj < 4; nj++) {
#pragma unroll
        for (int half = 0; half < 2; half++) {
            int n = n0g + tx * 8 + nj * 2 + half;
            float v[8];
#pragma unroll
            for (int mi = 0; mi < 8; mi++) { cv.u = acc[mi][nj]; v[mi] = cv.f[half]; }
            float* dst = g_y + (size_t)n * COUT_ + m0 + ty8;
            *(float4*)(dst + 0) = make_float4(v[0], v[1], v[2], v[3]);
            *(float4*)(dst + 4) = make_float4(v[4], v[5], v[6], v[7]);
        }
    }
}

// ---------------------------------------------------------------------------
// WTA + Gaussian lateral feedback gating (27 pixels per block)
// ---------------------------------------------------------------------------
#define SYP 388

__global__ __launch_bounds__(256) void wta_lfb_kernel(float* __restrict__ out) {
    __shared__ float sy[27 * SYP];
    __shared__ int   wcnt[27];
    __shared__ int   wlist[27][4];

    const int tid = threadIdx.x;
    const int b   = blockIdx.z;
    const int h   = blockIdx.y;
    const int w0  = blockIdx.x * 27;

    const size_t base = ((size_t)b * IMG_N + h * HIN_ + w0) * COUT_;

    for (int i4 = tid; i4 < 27 * 96; i4 += 256) {
        float4 v = *(const float4*)(g_y + base + (size_t)i4 * 4);
        int j  = i4 / 96;
        int c4 = i4 - j * 96;
        *(float4*)&sy[j * SYP + c4 * 4] = v;
    }
    if (tid < 27) wcnt[tid] = 0;
    __syncthreads();

    const int wid  = tid >> 5;
    const int lane = tid & 31;
    for (int j = wid; j < 27; j += 8) {
        const float* p = &sy[j * SYP];
        float mx = -3.4e38f;
#pragma unroll
        for (int q = 0; q < 12; q++) mx = fmaxf(mx, p[lane + q * 32]);
#pragma unroll
        for (int o = 16; o; o >>= 1) mx = fmaxf(mx, __shfl_xor_sync(0xffffffffu, mx, o));
#pragma unroll
        for (int q = 0; q < 12; q++) {
            int c = lane + q * 32;
            if (p[c] == mx) {
                int pos = atomicAdd(&wcnt[j], 1);
                if (pos < 4) wlist[j][pos] = c;
            }
        }
    }
    __syncthreads();

    const float inv2s2 = 1.0f / (2.0f * 191.0f * 191.0f);
    for (int i = tid; i < COUT_ * 27; i += 256) {
        int c = i / 27;
        int j = i - c * 27;
        float yv = sy[j * SYP + c];
        int nw = wcnt[j]; if (nw > 4) nw = 4;
        float lfb = 0.0f;
        for (int t = 0; t < nw; t++) {
            int d = wlist[j][t] - c;
            if (d >= -191 && d <= 192)
                lfb += __expf(-(float)(d * d) * inv2s2);
        }
        lfb = fminf(lfb, 1.0f);
        out[(((size_t)b * COUT_ + c) * HO_ + h) * HO_ + w0 + j] = lfb * yv;
    }
}

// ---------------------------------------------------------------------------
extern "C" void kernel_launch(void* const* d_in, const int* in_sizes, int n_in,
                              void* d_out, int out_size) {
    const float* x = (const float*)d_in[0];   // (16,256,56,56)
    const float* w = (const float*)d_in[1];   // (384,256,3,3)
    float* out = (float*)d_out;               // (16,384,54,54)

    copy_x_kernel<<<(unsigned)((XELEMS / 4 + 255) / 256), 256>>>(x);

    dim3 g1(B_SZ * 12, 3);                    // 192 n-tiles x 3 m-tiles
    conv_gemm_kernel<<<g1, 512>>>(w);

    dim3 g2(2, HO_, B_SZ);
    wta_lfb_kernel<<<g2, 256>>>(out);

    pad_kernel<<<1, 32>>>();                  // aligns ncu -s 5 onto the conv kernel
}